// round 2
// baseline (speedup 1.0000x reference)
#include <cuda_runtime.h>
#include <cuda_bf16.h>
#include <float.h>

// Problem constants (fixed by the reference)
#define BB 16
#define TT 1024
#define VV 4096
#define SS 256
#define NEGV (-1e30f)

// Scratch: p[b][t][s] = exp(logits[b,t,targets[b,s]] - lse[b,t])   (16 MB, L2-resident)
__device__ __align__(16) float g_p[(size_t)BB * TT * SS];

// ---------------------------------------------------------------------------
// Kernel 1: per-(b,t) row logsumexp + gather of 256 target columns.
// One block of 256 threads per row. Row staged in smem for the gather.
// Stores p = exp(lp) so the scan can run in the (scaled) probability domain.
// ---------------------------------------------------------------------------
__global__ __launch_bounds__(256) void lse_gather_kernel(
    const float* __restrict__ logits,
    const int* __restrict__ targets)
{
    const int row = blockIdx.x;          // row = b*TT + t
    const int b   = row >> 10;           // TT = 1024
    const int tid = threadIdx.x;

    __shared__ float srow[VV];           // 16 KB
    __shared__ float red[16];

    const float4* rp = reinterpret_cast<const float4*>(logits + (size_t)row * VV);

    float4 v0 = rp[tid];
    float4 v1 = rp[tid + 256];
    float4 v2 = rp[tid + 512];
    float4 v3 = rp[tid + 768];
    float4* s4 = reinterpret_cast<float4*>(srow);
    s4[tid]       = v0;
    s4[tid + 256] = v1;
    s4[tid + 512] = v2;
    s4[tid + 768] = v3;

    float mx = fmaxf(fmaxf(v0.x, v0.y), fmaxf(v0.z, v0.w));
    mx = fmaxf(mx, fmaxf(fmaxf(v1.x, v1.y), fmaxf(v1.z, v1.w)));
    mx = fmaxf(mx, fmaxf(fmaxf(v2.x, v2.y), fmaxf(v2.z, v2.w)));
    mx = fmaxf(mx, fmaxf(fmaxf(v3.x, v3.y), fmaxf(v3.z, v3.w)));

    #pragma unroll
    for (int o = 16; o > 0; o >>= 1)
        mx = fmaxf(mx, __shfl_xor_sync(0xFFFFFFFFu, mx, o));
    if ((tid & 31) == 0) red[tid >> 5] = mx;
    __syncthreads();
    float m = red[0];
    #pragma unroll
    for (int i = 1; i < 8; i++) m = fmaxf(m, red[i]);

    float sum = 0.0f;
    sum += __expf(v0.x - m) + __expf(v0.y - m) + __expf(v0.z - m) + __expf(v0.w - m);
    sum += __expf(v1.x - m) + __expf(v1.y - m) + __expf(v1.z - m) + __expf(v1.w - m);
    sum += __expf(v2.x - m) + __expf(v2.y - m) + __expf(v2.z - m) + __expf(v2.w - m);
    sum += __expf(v3.x - m) + __expf(v3.y - m) + __expf(v3.z - m) + __expf(v3.w - m);
    #pragma unroll
    for (int o = 16; o > 0; o >>= 1)
        sum += __shfl_xor_sync(0xFFFFFFFFu, sum, o);
    if ((tid & 31) == 0) red[8 + (tid >> 5)] = sum;
    __syncthreads();
    float tot = red[8];
    #pragma unroll
    for (int i = 1; i < 8; i++) tot += red[8 + i];

    const float lse = m + __logf(tot);

    const int tgt = targets[b * SS + tid];
    g_p[(size_t)row * SS + tid] = __expf(srow[tgt] - lse);
}

// ---------------------------------------------------------------------------
// Kernel 2: serial scan over T in the scaled-probability domain.
// One warp per batch; lane owns 8 consecutive states in registers:
//     A[j] ~= exp(alpha[lane*8+j]) * 2^-E     (per-lane scale E)
// Per step: A_new[j] = p[j]*(A[j] + A[j-1]); boundary via one __shfl_up.
// Rescale (power-of-2, bit tricks) every 4 steps; boundary factor
// fac = 2^(Eb-E) is constant between rescales (one exp2f per 4 steps).
// ---------------------------------------------------------------------------
struct ScanState {
    float A[8];
    int   E;       // our scale exponent
    int   Eb;      // left neighbor's scale exponent (refreshed at rescale)
    int   empty;   // 1 if lane is all-zero (scale meaningless)
    float fac;     // 2^(Eb - E), applied to incoming boundary value
};

__device__ __forceinline__ void rescale_lane(ScanState& st, int lane)
{
    float m = fmaxf(fmaxf(fmaxf(st.A[0], st.A[1]), fmaxf(st.A[2], st.A[3])),
                    fmaxf(fmaxf(st.A[4], st.A[5]), fmaxf(st.A[6], st.A[7])));
    if (m > 0.0f) {
        int e = (__float_as_int(m) >> 23) - 127;         // exponent of max
        float sc = __int_as_float((127 - e) << 23);      // exactly 2^-e
        #pragma unroll
        for (int j = 0; j < 8; j++) st.A[j] *= sc;
        st.E += e;
        st.empty = 0;
    } else {
        st.empty = 1;
    }
    int Enb     = __shfl_up_sync(0xFFFFFFFFu, st.E, 1);
    int nbEmpty = __shfl_up_sync(0xFFFFFFFFu, st.empty, 1);
    if (lane == 0) { Enb = st.E; nbEmpty = 1; }
    st.Eb = Enb;
    int dE = st.Eb - st.E;
    // If a (valid) left neighbor is >100 bits above us, our lane is
    // negligible: rebase to the neighbor's scale so fac stays finite.
    if (!st.empty && !nbEmpty && dE > 100) {
        float dn = exp2f((float)(-dE));
        #pragma unroll
        for (int j = 0; j < 8; j++) st.A[j] *= dn;
        st.E = st.Eb;
        dE = 0;
    }
    st.fac = st.empty ? 0.0f : exp2f((float)dE);
}

__device__ __forceinline__ void scan_step(ScanState& st, float4 pa, float4 pb,
                                          int t, int lane)
{
    float Ab = __shfl_up_sync(0xFFFFFFFFu, st.A[7], 1);
    if (lane == 0) Ab = (t == 0) ? 1.0f : 0.0f;   // virtual start state
    if (st.empty && Ab > 0.0f) {                  // adopt neighbor scale on first mass
        st.E = st.Eb;
        st.fac = 1.0f;
        st.empty = 0;
    }
    float inj = Ab * st.fac;
    float n0 = pa.x * (st.A[0] + inj);
    float n1 = pa.y * (st.A[1] + st.A[0]);
    float n2 = pa.z * (st.A[2] + st.A[1]);
    float n3 = pa.w * (st.A[3] + st.A[2]);
    float n4 = pb.x * (st.A[4] + st.A[3]);
    float n5 = pb.y * (st.A[5] + st.A[4]);
    float n6 = pb.z * (st.A[6] + st.A[5]);
    float n7 = pb.w * (st.A[7] + st.A[6]);
    st.A[0] = n0; st.A[1] = n1; st.A[2] = n2; st.A[3] = n3;
    st.A[4] = n4; st.A[5] = n5; st.A[6] = n6; st.A[7] = n7;
}

__global__ __launch_bounds__(32) void scan_kernel(
    const int* __restrict__ logits_lengths,
    const int* __restrict__ targets_lengths,
    float* __restrict__ out)
{
    const int b    = blockIdx.x;
    const int lane = threadIdx.x;
    const int L    = logits_lengths[b];   // in [961, 1024]
    const int tl   = targets_lengths[b];  // in [225, 256]

    const float4* pp =
        reinterpret_cast<const float4*>(g_p + (size_t)b * TT * SS) + lane * 2;
    // step t lives at pp[t*64] and pp[t*64 + 1]

    ScanState st;
    #pragma unroll
    for (int j = 0; j < 8; j++) st.A[j] = 0.0f;
    st.E = 0; st.Eb = 0; st.empty = 1; st.fac = 0.0f;

    float4 bufa[2][8], bufb[2][8];
    #pragma unroll
    for (int k = 0; k < 8; k++) {
        bufa[0][k] = pp[k * 64];
        bufb[0][k] = pp[k * 64 + 1];
    }

    const int nfull = L & ~7;
    int cur = 0;
    for (int tc = 0; tc < nfull; tc += 8, cur ^= 1) {
        const int tn = tc + 8;
        if (tn < TT) {
            #pragma unroll
            for (int k = 0; k < 8; k++) {
                bufa[cur ^ 1][k] = pp[(tn + k) * 64];
                bufb[cur ^ 1][k] = pp[(tn + k) * 64 + 1];
            }
        }
        #pragma unroll
        for (int k = 0; k < 8; k++) {
            if ((k & 3) == 0) rescale_lane(st, lane);
            scan_step(st, bufa[cur][k], bufb[cur][k], tc + k, lane);
        }
    }

    // tail: t in [nfull, L), p already in bufa/bufb[cur]
    const int tail = L - nfull;
    #pragma unroll
    for (int k = 0; k < 8; k++) {
        if (k < tail) {
            if ((k & 3) == 0) rescale_lane(st, lane);
            scan_step(st, bufa[cur][k], bufb[cur][k], nfull + k, lane);
        }
    }

    // readout alpha[tl-1] = (log2(A[rj]) + E) * ln2 from lane rl
    const int src = tl - 1;
    const int rl = src >> 3;
    const int rj = src & 7;          // warp-uniform
    float av = st.A[0];
    #pragma unroll
    for (int j = 1; j < 8; j++)
        if (rj == j) av = st.A[j];
    if (lane == rl) {
        float alpha = (log2f(av) + (float)st.E) * 0.6931471805599453f;
        atomicAdd(out, -alpha);
    }
}

// ---------------------------------------------------------------------------
extern "C" void kernel_launch(void* const* d_in, const int* in_sizes, int n_in,
                              void* d_out, int out_size)
{
    const float* logits          = (const float*)d_in[0];
    const int*   targets         = (const int*)d_in[1];
    const int*   logits_lengths  = (const int*)d_in[2];
    const int*   targets_lengths = (const int*)d_in[3];
    float*       out             = (float*)d_out;

    cudaMemsetAsync(out, 0, (size_t)out_size * sizeof(float));

    lse_gather_kernel<<<BB * TT, 256>>>(logits, targets);
    scan_kernel<<<BB, 32>>>(logits_lengths, targets_lengths, out);
}